// round 16
// baseline (speedup 1.0000x reference)
#include <cuda_runtime.h>

#define Bn 256
#define Sn 64
#define Dn 64
#define Fn 10
#define NCn 10
#define Pf 2016.0f

struct __align__(16) Smem {
    float E[Sn * Dn];       // embeddings
    float U[Sn * Dn];       // E@W1a + b1, later FH
    float V[Sn * Dn];       // E@W1b
    float W[65 * Dn];       // staging: W1a/W1b/freq_w1
    float cw2[Dn * Fn];     // comb_w2
    float fw2T[Fn * Dn];    // freq_w2 transposed [f][d]
    float cc[NCn * Dn];     // cluster centers
    float fr[Sn];           // per-token frequency
    float e2s[Sn];          // |e_s|^2
    float cn2[16];          // |c|^2
    float Hpart[16 * Dn];   // partial pair sums (16 groups)
    float Hsum[Dn];
    float csum[16];
    float dist[Sn * NCn];
    int   sid[Sn];
};

// ---- packed f32x2 helpers (sm_103a FFMA2 path; ptxas never emits it from C++) ----
__device__ __forceinline__ unsigned long long pk2(float lo, float hi) {
    unsigned long long r;
    asm("mov.b64 %0, {%1, %2};" : "=l"(r) : "f"(lo), "f"(hi));
    return r;
}
__device__ __forceinline__ void fma2(unsigned long long& d,
                                     unsigned long long a, unsigned long long b) {
    asm("fma.rn.f32x2 %0, %1, %2, %0;" : "+l"(d) : "l"(a), "l"(b));
}
__device__ __forceinline__ float upk_sum(unsigned long long p) {
    float lo, hi;
    asm("mov.b64 {%0, %1}, %2;" : "=f"(lo), "=f"(hi) : "l"(p));
    return lo + hi;
}

// 64x64 GEMM tile (4 rows x 16 cols per thread), k-packed FFMA2
__device__ __forceinline__ void gemm16p(const float4* __restrict__ E4,
                                        const float4* __restrict__ W4,
                                        int s0, int dblk, float acc[4][4]) {
    unsigned long long ap[4][4];
#pragma unroll
    for (int si = 0; si < 4; ++si)
#pragma unroll
        for (int c = 0; c < 4; ++c) ap[si][c] = 0ull;
#pragma unroll
    for (int kk = 0; kk < 16; ++kk) {
        float4 w0 = W4[(4 * kk + 0) * 16 + dblk];
        float4 w1 = W4[(4 * kk + 1) * 16 + dblk];
        float4 w2 = W4[(4 * kk + 2) * 16 + dblk];
        float4 w3 = W4[(4 * kk + 3) * 16 + dblk];
        unsigned long long wA0 = pk2(w0.x, w1.x), wA1 = pk2(w0.y, w1.y);
        unsigned long long wA2 = pk2(w0.z, w1.z), wA3 = pk2(w0.w, w1.w);
        unsigned long long wB0 = pk2(w2.x, w3.x), wB1 = pk2(w2.y, w3.y);
        unsigned long long wB2 = pk2(w2.z, w3.z), wB3 = pk2(w2.w, w3.w);
#pragma unroll
        for (int si = 0; si < 4; ++si) {
            float4 e = E4[(s0 + si) * 16 + kk];
            unsigned long long exy = pk2(e.x, e.y);   // natural reg pair
            unsigned long long ezw = pk2(e.z, e.w);
            fma2(ap[si][0], exy, wA0); fma2(ap[si][0], ezw, wB0);
            fma2(ap[si][1], exy, wA1); fma2(ap[si][1], ezw, wB1);
            fma2(ap[si][2], exy, wA2); fma2(ap[si][2], ezw, wB2);
            fma2(ap[si][3], exy, wA3); fma2(ap[si][3], ezw, wB3);
        }
    }
#pragma unroll
    for (int si = 0; si < 4; ++si)
#pragma unroll
        for (int c = 0; c < 4; ++c) acc[si][c] = upk_sum(ap[si][c]);
}

__global__ __launch_bounds__(256, 2)
void cate_enc_kernel(const int* __restrict__ ids, const float* __restrict__ table,
                     const float* __restrict__ cw1, const float* __restrict__ cb1,
                     const float* __restrict__ cw2g, const float* __restrict__ cb2,
                     const float* __restrict__ fw1, const float* __restrict__ fb1,
                     const float* __restrict__ fw2g, const float* __restrict__ fb2,
                     const float* __restrict__ ccg, const float* __restrict__ catf,
                     const float* __restrict__ tot, float* __restrict__ out) {
    extern __shared__ char smraw[];
    Smem& sm = *reinterpret_cast<Smem*>(smraw);
    const int t = threadIdx.x;
    const int b = blockIdx.x;

    // ---- phase 0a: ids + freqs, stage W1a and small weights ----
    if (t < Sn) {
        int id = ids[b * Sn + t];
        sm.sid[t] = id;
        sm.fr[t] = catf[id] / tot[0];
    }
    {
        float4* W4 = (float4*)sm.W;
        const float4* g4 = (const float4*)cw1;   // rows 0..63 = W1a
#pragma unroll
        for (int c = 0; c < 4; ++c) W4[t + 256 * c] = g4[t + 256 * c];
        if (t < 160) {
            ((float4*)sm.cw2)[t] = ((const float4*)cw2g)[t];
            ((float4*)sm.cc)[t]  = ((const float4*)ccg)[t];
        }
        for (int i = t; i < Dn * Fn; i += 256) {   // fw2T[f*64+d] = fw2[d*10+f]
            int f = i >> 6, d = i & 63;
            sm.fw2T[i] = fw2g[d * Fn + f];
        }
    }
    __syncthreads();

    // ---- phase 0b: embedding gather ----
    {
        float4* E4 = (float4*)sm.E;
        const float4* T4 = (const float4*)table;
#pragma unroll
        for (int c = 0; c < 4; ++c) {
            int lin = t + 256 * c;
            int s = lin >> 4, q = lin & 15;
            E4[lin] = T4[sm.sid[s] * 16 + q];
        }
    }
    __syncthreads();

    const int sblk = t >> 4, dblk = t & 15;
    const int s0 = sblk * 4;

    // ---- phase 1: U = E @ W1a + b1 ----
    {
        float acc[4][4];
        gemm16p((const float4*)sm.E, (const float4*)sm.W, s0, dblk, acc);
        float4 bv = ((const float4*)cb1)[dblk];
        float4* U4 = (float4*)sm.U;
#pragma unroll
        for (int si = 0; si < 4; ++si) {
            float4 o;
            o.x = acc[si][0] + bv.x; o.y = acc[si][1] + bv.y;
            o.z = acc[si][2] + bv.z; o.w = acc[si][3] + bv.w;
            U4[(s0 + si) * 16 + dblk] = o;
        }
    }
    __syncthreads();

    // ---- phase 2: stage W1b ----
    {
        float4* W4 = (float4*)sm.W;
        const float4* g4 = (const float4*)cw1;
#pragma unroll
        for (int c = 0; c < 4; ++c) W4[t + 256 * c] = g4[1024 + t + 256 * c];
    }
    __syncthreads();

    // ---- phase 3: V = E @ W1b ----
    {
        float acc[4][4];
        gemm16p((const float4*)sm.E, (const float4*)sm.W, s0, dblk, acc);
        float4* V4 = (float4*)sm.V;
#pragma unroll
        for (int si = 0; si < 4; ++si) {
            float4 o;
            o.x = acc[si][0]; o.y = acc[si][1]; o.z = acc[si][2]; o.w = acc[si][3];
            V4[(s0 + si) * 16 + dblk] = o;
        }
    }
    __syncthreads();

    // ---- phase 4: stage freq_w1; balanced float4 pair sum overlaps ----
    {
        float4* W4 = (float4*)sm.W;
        const float4* g4 = (const float4*)fw1;
#pragma unroll
        for (int c = 0; c < 4; ++c) W4[t + 256 * c] = g4[t + 256 * c];
        if (t < 16) W4[1024 + t] = g4[1024 + t];
    }
    {   // thread (g, c) owns i in {g, 31-g, 32+g, 63-g} -> exactly 126 iters
        const float4* U4 = (const float4*)sm.U;
        const float4* V4 = (const float4*)sm.V;
        const int g = t >> 4, c = t & 15;
        const int iset[4] = {g, 31 - g, 32 + g, 63 - g};
        float4 a = {0.f, 0.f, 0.f, 0.f};
#pragma unroll
        for (int q = 0; q < 4; ++q) {
            int i = iset[q];
            float4 u = U4[i * 16 + c];
#pragma unroll 4
            for (int j = i + 1; j < Sn; ++j) {
                float4 v = V4[j * 16 + c];
                a.x += fmaxf(u.x + v.x, 0.f);
                a.y += fmaxf(u.y + v.y, 0.f);
                a.z += fmaxf(u.z + v.z, 0.f);
                a.w += fmaxf(u.w + v.w, 0.f);
            }
        }
        ((float4*)sm.Hpart)[g * 16 + c] = a;
    }
    __syncthreads();

    // ---- phase 5: reduce Hsum, |e|^2, |c|^2 ----
    if (t < Sn) {
        float s = 0.f;
#pragma unroll
        for (int g = 0; g < 16; ++g) s += sm.Hpart[g * Dn + t];
        sm.Hsum[t] = s;
        const float4* E4 = (const float4*)sm.E;
        unsigned long long p = 0ull;
#pragma unroll
        for (int kk = 0; kk < 16; ++kk) {
            float4 e = E4[t * 16 + kk];
            unsigned long long exy = pk2(e.x, e.y), ezw = pk2(e.z, e.w);
            fma2(p, exy, exy); fma2(p, ezw, ezw);
        }
        sm.e2s[t] = upk_sum(p);
    } else if (t < Sn + NCn) {
        int c = t - Sn;
        const float4* C4 = (const float4*)sm.cc;
        unsigned long long p = 0ull;
#pragma unroll
        for (int kk = 0; kk < 16; ++kk) {
            float4 e = C4[c * 16 + kk];
            unsigned long long exy = pk2(e.x, e.y), ezw = pk2(e.z, e.w);
            fma2(p, exy, exy); fma2(p, ezw, ezw);
        }
        sm.cn2[c] = upk_sum(p);
    }
    __syncthreads();

    // ---- phase 6: FH -> U; distances; csum ----
    {
        float acc[4][4];
        gemm16p((const float4*)sm.E, (const float4*)sm.W, s0, dblk, acc);
        float4 fbv = ((const float4*)fb1)[dblk];
        float4 wl  = ((const float4*)(sm.W + 64 * Dn))[dblk];
        float4* U4 = (float4*)sm.U;
#pragma unroll
        for (int si = 0; si < 4; ++si) {
            float fq = sm.fr[s0 + si];
            float4 o;
            o.x = fmaxf(acc[si][0] + fq * wl.x + fbv.x, 0.f);
            o.y = fmaxf(acc[si][1] + fq * wl.y + fbv.y, 0.f);
            o.z = fmaxf(acc[si][2] + fq * wl.z + fbv.z, 0.f);
            o.w = fmaxf(acc[si][3] + fq * wl.w + fbv.w, 0.f);
            U4[(s0 + si) * 16 + dblk] = o;
        }
    }
    {
        const int s = t & 63, g = t >> 6;
        const float4* E4 = (const float4*)sm.E;
        const float4* C4 = (const float4*)sm.cc;
        for (int c = g; c < NCn; c += 4) {
            unsigned long long p = 0ull;
#pragma unroll
            for (int kk = 0; kk < 16; ++kk) {
                float4 e = E4[s * 16 + kk];
                float4 cv = C4[c * 16 + kk];
                fma2(p, pk2(e.x, e.y), pk2(cv.x, cv.y));
                fma2(p, pk2(e.z, e.w), pk2(cv.z, cv.w));
            }
            float d2 = sm.e2s[s] + sm.cn2[c] - 2.f * upk_sum(p);
            sm.dist[s * NCn + c] = sqrtf(fmaxf(d2, 0.f));
        }
    }
    if (t < NCn) {
        float s = 0.f;
#pragma unroll 8
        for (int d = 0; d < Dn; ++d) s += sm.Hsum[d] * sm.cw2[d * Fn + t];
        sm.csum[t] = s + Pf * cb2[t];
    }
    __syncthreads();

    // ---- phase 7: softmax(-dist) per token ----
    if (t < Sn) {
        float mn = sm.dist[t * NCn];
#pragma unroll
        for (int c = 1; c < NCn; ++c) mn = fminf(mn, sm.dist[t * NCn + c]);
        float e[NCn]; float ssum = 0.f;
#pragma unroll
        for (int c = 0; c < NCn; ++c) { e[c] = __expf(mn - sm.dist[t * NCn + c]); ssum += e[c]; }
        float inv = 1.f / ssum;
#pragma unroll
        for (int c = 0; c < NCn; ++c) sm.dist[t * NCn + c] = e[c] * inv;
    }
    __syncthreads();

    // ---- phase 8: final output (packed fw2T dot) ----
    const float invP = 1.f / (Pf + 2.f);
    const float4* FH4 = (const float4*)sm.U;
    const float4* W2T = (const float4*)sm.fw2T;
    for (int lin = t; lin < Sn * Fn; lin += 256) {
        int s = lin / Fn, f = lin - s * Fn;
        unsigned long long p0 = 0ull, p1 = 0ull;
#pragma unroll 4
        for (int kk = 0; kk < 16; ++kk) {
            float4 h = FH4[s * 16 + kk];
            float4 w = W2T[f * 16 + kk];
            fma2(p0, pk2(h.x, h.y), pk2(w.x, w.y));
            fma2(p1, pk2(h.z, h.w), pk2(w.z, w.w));
        }
        float ff = upk_sum(p0) + upk_sum(p1);
        out[b * (Sn * Fn) + lin] = (ff + fb2[f] + sm.csum[f] + sm.dist[lin]) * invP;
    }
}

extern "C" void kernel_launch(void* const* d_in, const int* in_sizes, int n_in,
                              void* d_out, int out_size) {
    const int*   ids  = (const int*)d_in[0];
    const float* tab  = (const float*)d_in[1];
    const float* cw1  = (const float*)d_in[2];
    const float* cb1  = (const float*)d_in[3];
    const float* cw2  = (const float*)d_in[4];
    const float* cb2  = (const float*)d_in[5];
    const float* fw1  = (const float*)d_in[6];
    const float* fb1  = (const float*)d_in[7];
    const float* fw2  = (const float*)d_in[8];
    const float* fb2  = (const float*)d_in[9];
    const float* cc   = (const float*)d_in[10];
    const float* catf = (const float*)d_in[11];
    const float* tot  = (const float*)d_in[12];
    float* out = (float*)d_out;

    cudaFuncSetAttribute(cate_enc_kernel,
                         cudaFuncAttributeMaxDynamicSharedMemorySize,
                         (int)sizeof(Smem));
    cate_enc_kernel<<<Bn, 256, sizeof(Smem)>>>(ids, tab, cw1, cb1, cw2, cb2,
                                               fw1, fb1, fw2, fb2, cc, catf,
                                               tot, out);
}